// round 14
// baseline (speedup 1.0000x reference)
#include <cuda_runtime.h>
#include <cstdint>

// PQLayer: x:(B,512) fp32, C:(64,256,8) fp32.
// codes == one_hot(argmax_k <x_bm, C_mk>); x_hat row == C[m,kmax,:].
// R12: decouple the zero sweep (pure STG stream, issued FIRST so DRAM drains
// under the argmax) from the one-hot scatter (1 scalar STG per row, after
// argmax). Kills the per-chunk s_kb LDS + compare in the sweep (alu was 46%).

#define FEAT 512
#define Mn   64
#define Kn   256
#define Dn   8
#define TPB  128
#define BPT  2
#define ROWS (TPB * BPT)   // 256 b-rows per block

// ---- packed f32x2 helpers (Blackwell sm_103a; FFMA2 only via PTX) ----
__device__ __forceinline__ unsigned long long f2_mul(unsigned long long a,
                                                     unsigned long long b) {
    unsigned long long d;
    asm("mul.rn.f32x2 %0, %1, %2;" : "=l"(d) : "l"(a), "l"(b));
    return d;
}
__device__ __forceinline__ unsigned long long f2_fma(unsigned long long a,
                                                     unsigned long long b,
                                                     unsigned long long c) {
    unsigned long long d;
    asm("fma.rn.f32x2 %0, %1, %2, %3;" : "=l"(d) : "l"(a), "l"(b), "l"(c));
    return d;
}
__device__ __forceinline__ float2 f2_unpack(unsigned long long v) {
    float2 r;
    asm("mov.b64 {%0, %1}, %2;" : "=f"(r.x), "=f"(r.y) : "l"(v));
    return r;
}

__global__ void __launch_bounds__(TPB, 12)
pq_kernel(const float* __restrict__ x,
          const float* __restrict__ C,
          float* __restrict__ xhat,    // may be null
          float* __restrict__ codes,   // may be null
          int nB)
{
    __shared__ ulonglong2 sC[Kn * 2];   // 8 KB codebook tile for this m

    const int m  = blockIdx.y;
    const int b0 = blockIdx.x * ROWS;
    const bool full = (b0 + ROWS) <= nB;   // B % ROWS == 0 in practice

    // Kick off codebook staging loads first (LDG in flight)...
    const ulonglong2* Cg = reinterpret_cast<const ulonglong2*>(C + (size_t)m * Kn * Dn);
    #pragma unroll
    for (int i = threadIdx.x; i < Kn * 2; i += TPB) sC[i] = Cg[i];

    // ...then flood the DRAM pipe with the zero sweep (depends on nothing).
    // Coalesced: threads 0..63 cover the 64 float4 chunks of one b-row.
    const size_t row_stride4 = (size_t)Mn * Kn / 4;   // float4 between b-rows
    if (codes) {
        const float4 z = make_float4(0.f, 0.f, 0.f, 0.f);
        float4* p = reinterpret_cast<float4*>(codes)
                    + (((size_t)b0 * Mn + m) * Kn) / 4
                    + (size_t)(threadIdx.x >> 6) * row_stride4
                    + (threadIdx.x & 63);
        const size_t pstep = 2 * row_stride4;          // 2 rows per iteration step
        if (full) {
            #pragma unroll 8
            for (int j = 0; j < ROWS / 2; ++j, p += pstep) *p = z;
        } else {
            int r = threadIdx.x >> 6;
            for (int j = 0; j < ROWS / 2 && b0 + r < nB; ++j, r += 2, p += pstep) *p = z;
        }
    }
    __syncthreads();   // sC ready; also orders sweep before the later scatter

    // Load x for BPT rows: row t at b0 + tid + t*TPB
    unsigned long long xp[BPT][4];
    #pragma unroll
    for (int t = 0; t < BPT; ++t) {
        const int b = b0 + threadIdx.x + t * TPB;
        if (full || b < nB) {
            const ulonglong2* xg =
                reinterpret_cast<const ulonglong2*>(x + (size_t)b * FEAT + m * Dn);
            ulonglong2 xl = xg[0];
            ulonglong2 xh = xg[1];
            xp[t][0] = xl.x; xp[t][1] = xl.y; xp[t][2] = xh.x; xp[t][3] = xh.y;
        } else {
            xp[t][0] = xp[t][1] = xp[t][2] = xp[t][3] = 0ull;
        }
    }

    float best[BPT];
    int   kb[BPT];
    #pragma unroll
    for (int t = 0; t < BPT; ++t) { best[t] = -3.4e38f; kb[t] = 0; }

    // Argmax: one broadcast codeword LDS pair feeds BPT dot products.
    #pragma unroll 4
    for (int k = 0; k < Kn; ++k) {
        const ulonglong2 c01 = sC[2 * k];
        const ulonglong2 c23 = sC[2 * k + 1];
        #pragma unroll
        for (int t = 0; t < BPT; ++t) {
            unsigned long long acc = f2_mul(xp[t][0], c01.x);
            acc = f2_fma(xp[t][1], c01.y, acc);
            acc = f2_fma(xp[t][2], c23.x, acc);
            acc = f2_fma(xp[t][3], c23.y, acc);
            float2 ab = f2_unpack(acc);
            float dot = ab.x + ab.y;
            if (dot > best[t]) { best[t] = dot; kb[t] = k; }  // strict > => first idx
        }
    }

    // Ensure every thread's zero sweep is complete (block-scope ordering)
    // before the same-address 1.0 scatters. (Cheap: argmax already drained it.)
    __syncthreads();

    #pragma unroll
    for (int t = 0; t < BPT; ++t) {
        const int b = b0 + threadIdx.x + t * TPB;
        if (full || b < nB) {
            // x_hat row from the smem codebook
            if (xhat) {
                ulonglong2* o =
                    reinterpret_cast<ulonglong2*>(xhat + (size_t)b * FEAT + m * Dn);
                o[0] = sC[2 * kb[t]];
                o[1] = sC[2 * kb[t] + 1];
            }
            // the single hot element of this codes row
            if (codes)
                codes[(size_t)b * Mn * Kn + (size_t)m * Kn + kb[t]] = 1.0f;
        }
    }
}

extern "C" void kernel_launch(void* const* d_in, const int* in_sizes, int n_in,
                              void* d_out, int out_size)
{
    // Resolve inputs by size: x has B*512 elems, C has 64*256*8 = 131072 elems.
    const float* x = (const float*)d_in[0];
    const float* C = (const float*)d_in[1];
    int x_size = in_sizes[0];
    if (n_in >= 2 && in_sizes[0] == Mn * Kn * Dn && in_sizes[1] != Mn * Kn * Dn) {
        x = (const float*)d_in[1];
        C = (const float*)d_in[0];
        x_size = in_sizes[1];
    }
    const int nB = x_size / FEAT;

    const long long XH = (long long)nB * FEAT;        // x_hat elems
    const long long CD = (long long)nB * Mn * Kn;     // codes elems

    float* out   = (float*)d_out;
    float* xhat  = nullptr;
    float* codes = nullptr;
    if ((long long)out_size == XH + CD)      { xhat = out; codes = out + XH; }
    else if ((long long)out_size == XH)      { xhat = out; }
    else if ((long long)out_size == CD)      { codes = out; }
    else                                     { xhat = out; codes = out + XH; }

    dim3 grid((nB + ROWS - 1) / ROWS, Mn);
    pq_kernel<<<grid, TPB>>>(x, C, xhat, codes, nB);
}

// round 16
// speedup vs baseline: 1.2924x; 1.2924x over previous
#include <cuda_runtime.h>
#include <cstdint>

// PQLayer: x:(B,512) fp32, C:(64,256,8) fp32.
// codes == one_hot(argmax_k <x_bm, C_mk>); x_hat row == C[m,kmax,:].
// R14 = R7 fused structure (best known, 191us) +
//   (1) __launch_bounds__(128,12) regcap for occupancy 55->68%,
//   (2) consecutive-row sweep with int4 kb prefetch (1 LDS.128 per 4 rows),
//   (3) streaming cache hints (.cs) on the big one-way streams.

#define FEAT 512
#define Mn   64
#define Kn   256
#define Dn   8
#define TPB  128
#define BPT  2
#define ROWS (TPB * BPT)   // 256 b-rows per block

// ---- packed f32x2 helpers (Blackwell sm_103a; FFMA2 only via PTX) ----
__device__ __forceinline__ unsigned long long f2_mul(unsigned long long a,
                                                     unsigned long long b) {
    unsigned long long d;
    asm("mul.rn.f32x2 %0, %1, %2;" : "=l"(d) : "l"(a), "l"(b));
    return d;
}
__device__ __forceinline__ unsigned long long f2_fma(unsigned long long a,
                                                     unsigned long long b,
                                                     unsigned long long c) {
    unsigned long long d;
    asm("fma.rn.f32x2 %0, %1, %2, %3;" : "=l"(d) : "l"(a), "l"(b), "l"(c));
    return d;
}
__device__ __forceinline__ float2 f2_unpack(unsigned long long v) {
    float2 r;
    asm("mov.b64 {%0, %1}, %2;" : "=f"(r.x), "=f"(r.y) : "l"(v));
    return r;
}

// ---- streaming (evict-first) 16B global accessors ----
__device__ __forceinline__ void ldg_cs_128(const void* p,
                                           unsigned long long& a,
                                           unsigned long long& b) {
    asm("ld.global.cs.v2.u64 {%0, %1}, [%2];" : "=l"(a), "=l"(b) : "l"(p));
}
__device__ __forceinline__ void stg_cs_128(void* p,
                                           unsigned long long a,
                                           unsigned long long b) {
    asm("st.global.cs.v2.u64 [%0], {%1, %2};" :: "l"(p), "l"(a), "l"(b));
}
__device__ __forceinline__ void stg_cs_f4(void* p, float x, float y, float z, float w) {
    asm("st.global.cs.v4.f32 [%0], {%1, %2, %3, %4};"
        :: "l"(p), "f"(x), "f"(y), "f"(z), "f"(w));
}

__global__ void __launch_bounds__(TPB, 12)
pq_kernel(const float* __restrict__ x,
          const float* __restrict__ C,
          float* __restrict__ xhat,    // may be null
          float* __restrict__ codes,   // may be null
          int nB)
{
    __shared__ ulonglong2 sC[Kn * 2];   // 8 KB codebook tile for this m
    __shared__ int s_kb[ROWS];          // per-row argmax, int for LDS.128 prefetch

    const int m  = blockIdx.y;
    const int b0 = blockIdx.x * ROWS;
    const bool full = (b0 + ROWS) <= nB;   // B % ROWS == 0 in practice

    // Stage C[m] into smem (L2-cached; reused by 64 blocks)
    const ulonglong2* Cg = reinterpret_cast<const ulonglong2*>(C + (size_t)m * Kn * Dn);
    #pragma unroll
    for (int i = threadIdx.x; i < Kn * 2; i += TPB) sC[i] = Cg[i];
    __syncthreads();

    // Load x for BPT rows (streaming: read-once): row t at b0 + tid + t*TPB
    unsigned long long xp[BPT][4];
    #pragma unroll
    for (int t = 0; t < BPT; ++t) {
        const int b = b0 + threadIdx.x + t * TPB;
        if (full || b < nB) {
            const char* xg = reinterpret_cast<const char*>(x + (size_t)b * FEAT + m * Dn);
            ldg_cs_128(xg,      xp[t][0], xp[t][1]);
            ldg_cs_128(xg + 16, xp[t][2], xp[t][3]);
        } else {
            xp[t][0] = xp[t][1] = xp[t][2] = xp[t][3] = 0ull;
        }
    }

    float best[BPT];
    int   kb[BPT];
    #pragma unroll
    for (int t = 0; t < BPT; ++t) { best[t] = -3.4e38f; kb[t] = 0; }

    // Argmax: one broadcast codeword LDS pair feeds BPT dot products.
    #pragma unroll 4
    for (int k = 0; k < Kn; ++k) {
        const ulonglong2 c01 = sC[2 * k];
        const ulonglong2 c23 = sC[2 * k + 1];
        #pragma unroll
        for (int t = 0; t < BPT; ++t) {
            unsigned long long acc = f2_mul(xp[t][0], c01.x);
            acc = f2_fma(xp[t][1], c01.y, acc);
            acc = f2_fma(xp[t][2], c23.x, acc);
            acc = f2_fma(xp[t][3], c23.y, acc);
            float2 ab = f2_unpack(acc);
            float dot = ab.x + ab.y;
            if (dot > best[t]) { best[t] = dot; kb[t] = k; }  // strict > => first idx
        }
    }

    // x_hat rows straight from the smem codebook (streaming store)
    if (xhat) {
        #pragma unroll
        for (int t = 0; t < BPT; ++t) {
            const int b = b0 + threadIdx.x + t * TPB;
            if (full || b < nB) {
                char* o = reinterpret_cast<char*>(xhat + (size_t)b * FEAT + m * Dn);
                ulonglong2 v0 = sC[2 * kb[t]];
                ulonglong2 v1 = sC[2 * kb[t] + 1];
                stg_cs_128(o,      v0.x, v0.y);
                stg_cs_128(o + 16, v1.x, v1.y);
            }
        }
    }

    if (codes) {
        #pragma unroll
        for (int t = 0; t < BPT; ++t) s_kb[threadIdx.x + t * TPB] = kb[t];
        __syncthreads();

        // Fused one-hot sweep. Thread (h2 = tid>>6) covers rows [h2*128, h2*128+128)
        // consecutively; c4 = tid&63 is its fixed float4 chunk within each row.
        // kb for 4 rows prefetched with one LDS.128.
        const int c4 = threadIdx.x & 63;
        const int r0 = (threadIdx.x >> 6) * (ROWS / 2);
        const size_t row_stride4 = (size_t)Mn * Kn / 4;   // float4 between b-rows
        float4* p = reinterpret_cast<float4*>(codes) +
                    (((size_t)b0 * Mn + m) * Kn) / 4 +
                    (size_t)r0 * row_stride4 + c4;
        const int4* kb4p = reinterpret_cast<const int4*>(&s_kb[r0]);

        #pragma unroll 2
        for (int j4 = 0; j4 < (ROWS / 2) / 4; ++j4) {
            const int4 k4 = kb4p[j4];                      // broadcast LDS.128
            const int rbase = r0 + j4 * 4;
            if (!full && (b0 + rbase >= nB)) break;
            #pragma unroll
            for (int u = 0; u < 4; ++u) {
                const int kbr = (u == 0) ? k4.x : (u == 1) ? k4.y
                              : (u == 2) ? k4.z : k4.w;
                if (!full && (b0 + rbase + u >= nB)) break;
                float vx = 0.f, vy = 0.f, vz = 0.f, vw = 0.f;
                if ((kbr >> 2) == c4) {                    // rare (1/64) hit path
                    const int lane = kbr & 3;
                    vx = (lane == 0) ? 1.0f : 0.0f;
                    vy = (lane == 1) ? 1.0f : 0.0f;
                    vz = (lane == 2) ? 1.0f : 0.0f;
                    vw = (lane == 3) ? 1.0f : 0.0f;
                }
                stg_cs_f4(p + (size_t)u * row_stride4, vx, vy, vz, vw);
            }
            p += 4 * row_stride4;
        }
    }
}

extern "C" void kernel_launch(void* const* d_in, const int* in_sizes, int n_in,
                              void* d_out, int out_size)
{
    // Resolve inputs by size: x has B*512 elems, C has 64*256*8 = 131072 elems.
    const float* x = (const float*)d_in[0];
    const float* C = (const float*)d_in[1];
    int x_size = in_sizes[0];
    if (n_in >= 2 && in_sizes[0] == Mn * Kn * Dn && in_sizes[1] != Mn * Kn * Dn) {
        x = (const float*)d_in[1];
        C = (const float*)d_in[0];
        x_size = in_sizes[1];
    }
    const int nB = x_size / FEAT;

    const long long XH = (long long)nB * FEAT;        // x_hat elems
    const long long CD = (long long)nB * Mn * Kn;     // codes elems

    float* out   = (float*)d_out;
    float* xhat  = nullptr;
    float* codes = nullptr;
    if ((long long)out_size == XH + CD)      { xhat = out; codes = out + XH; }
    else if ((long long)out_size == XH)      { xhat = out; }
    else if ((long long)out_size == CD)      { codes = out; }
    else                                     { xhat = out; codes = out + XH; }

    dim3 grid((nB + ROWS - 1) / ROWS, Mn);
    pq_kernel<<<grid, TPB>>>(x, C, xhat, codes, nB);
}